// round 1
// baseline (speedup 1.0000x reference)
#include <cuda_runtime.h>
#include <cuda_bf16.h>
#include <cstdint>

#define B_ 256
#define T_ 512
#define I_ 64
#define R_ 2048
#define O_ 10

#define SA_STRIDE 36   // 32 + 4 pad: LDS banks (4g + tg) all distinct
#define SB_STRIDE 72   // 64 + 8 pad: LDS banks (8k + g) all distinct

// Ping-pong hidden state buffers (scratch; allocation-free rule => __device__ global)
__device__ __align__(128) float g_H[2][B_ * R_];

__device__ __forceinline__ uint32_t f2tf(float f) {
    uint32_t u;
    asm("cvt.rna.tf32.f32 %0, %1;" : "=r"(u) : "f"(f));
    return u;
}

__device__ __forceinline__ void cp16(void* dst, const void* src) {
    uint32_t d = (uint32_t)__cvta_generic_to_shared(dst);
    asm volatile("cp.async.cg.shared.global [%0], [%1], 16;\n" :: "r"(d), "l"(src));
}

__global__ void esn_zero() {
    int i = blockIdx.x * blockDim.x + threadIdx.x;
    reinterpret_cast<float4*>(g_H[0])[i] = make_float4(0.f, 0.f, 0.f, 0.f);
}

// One scan step: H_new = 0.5*H + 0.5*tanh([H | x_t] @ [W_res ; W_in])
// GEMM: M=256, N=2048, virtual K = 2048 (W_res) + 64 (W_in) = 66 k-tiles of 32.
// Tile 64x64, 4 warps in 2x2, each warp 32x32 via m16n8k8 tf32 mma.
__global__ __launch_bounds__(128) void esn_step(
    const float* __restrict__ x, const float* __restrict__ W_in,
    const float* __restrict__ W_res, int t)
{
    const float* __restrict__ Hold = g_H[t & 1];
    float* __restrict__ Hnew = g_H[(t + 1) & 1];

    __shared__ float sA[2][64 * SA_STRIDE];
    __shared__ float sB[2][32 * SB_STRIDE];

    const int tid = threadIdx.x;
    const int bn = blockIdx.x;   // N tile (of 32)
    const int bm = blockIdx.y;   // M tile (of 4)
    const int warp = tid >> 5, lane = tid & 31;
    const int g = lane >> 2, tg = lane & 3;
    const int wm = warp & 1, wn = warp >> 1;

    float c[2][4][4];
#pragma unroll
    for (int mi = 0; mi < 2; mi++)
#pragma unroll
        for (int ni = 0; ni < 4; ni++)
#pragma unroll
            for (int i = 0; i < 4; i++) c[mi][ni][i] = 0.f;

    auto issue_tile = [&](int kt) {
        float* dA = sA[kt & 1];
        float* dB = sB[kt & 1];
        // A tile: 64 rows x 32 floats = 512 float4, 4 per thread
#pragma unroll
        for (int it = 0; it < 4; it++) {
            int e = it * 128 + tid;
            int row = e >> 3, c4 = e & 7;
            const float* src;
            if (kt < 64)
                src = Hold + (size_t)(bm * 64 + row) * R_ + kt * 32 + c4 * 4;
            else
                src = x + (size_t)(bm * 64 + row) * (T_ * I_) + (size_t)t * I_
                        + (kt - 64) * 32 + c4 * 4;
            cp16(dA + row * SA_STRIDE + c4 * 4, src);
        }
        // B tile: 32 rows x 64 floats = 512 float4, 4 per thread
#pragma unroll
        for (int it = 0; it < 4; it++) {
            int e = it * 128 + tid;
            int row = e >> 4, c4 = e & 15;
            const float* src;
            if (kt < 64)
                src = W_res + (size_t)(kt * 32 + row) * R_ + bn * 64 + c4 * 4;
            else
                src = W_in + (size_t)((kt - 64) * 32 + row) * R_ + bn * 64 + c4 * 4;
            cp16(dB + row * SB_STRIDE + c4 * 4, src);
        }
        asm volatile("cp.async.commit_group;\n" ::);
    };

    issue_tile(0);

    for (int kt = 0; kt < 66; kt++) {
        if (kt + 1 < 66) {
            issue_tile(kt + 1);
            asm volatile("cp.async.wait_group 1;\n" ::);
        } else {
            asm volatile("cp.async.wait_group 0;\n" ::);
        }
        __syncthreads();

        const float* A  = sA[kt & 1];
        const float* Bs = sB[kt & 1];
#pragma unroll
        for (int k8 = 0; k8 < 4; k8++) {
            uint32_t a[2][4];
#pragma unroll
            for (int mi = 0; mi < 2; mi++) {
                const float* ap = A + (wm * 32 + mi * 16 + g) * SA_STRIDE + k8 * 8 + tg;
                a[mi][0] = f2tf(ap[0]);
                a[mi][1] = f2tf(ap[8 * SA_STRIDE]);
                a[mi][2] = f2tf(ap[4]);
                a[mi][3] = f2tf(ap[8 * SA_STRIDE + 4]);
            }
            uint32_t b[4][2];
#pragma unroll
            for (int ni = 0; ni < 4; ni++) {
                const float* bp = Bs + (k8 * 8 + tg) * SB_STRIDE + wn * 32 + ni * 8 + g;
                b[ni][0] = f2tf(bp[0]);
                b[ni][1] = f2tf(bp[4 * SB_STRIDE]);
            }
#pragma unroll
            for (int mi = 0; mi < 2; mi++)
#pragma unroll
                for (int ni = 0; ni < 4; ni++)
                    asm volatile(
                        "mma.sync.aligned.m16n8k8.row.col.f32.tf32.tf32.f32 "
                        "{%0,%1,%2,%3}, {%4,%5,%6,%7}, {%8,%9}, {%0,%1,%2,%3};\n"
                        : "+f"(c[mi][ni][0]), "+f"(c[mi][ni][1]),
                          "+f"(c[mi][ni][2]), "+f"(c[mi][ni][3])
                        : "r"(a[mi][0]), "r"(a[mi][1]), "r"(a[mi][2]), "r"(a[mi][3]),
                          "r"(b[ni][0]), "r"(b[ni][1]));
        }
        __syncthreads();
    }

    // Epilogue: leaky-integrator tanh update
#pragma unroll
    for (int mi = 0; mi < 2; mi++) {
#pragma unroll
        for (int ni = 0; ni < 4; ni++) {
#pragma unroll
            for (int i = 0; i < 4; i++) {
                int row = bm * 64 + wm * 32 + mi * 16 + g + ((i >> 1) << 3);
                int col = bn * 64 + wn * 32 + ni * 8 + tg * 2 + (i & 1);
                float ho = Hold[(size_t)row * R_ + col];
                Hnew[(size_t)row * R_ + col] = 0.5f * ho + 0.5f * tanhf(c[mi][ni][i]);
            }
        }
    }
}

// out[b, :] = h_last[b, :] @ W_out + b_out   (fp32, deterministic reduction)
__global__ void esn_readout(const float* __restrict__ W_out,
                            const float* __restrict__ b_out,
                            float* __restrict__ out)
{
    int b = blockIdx.x, tid = threadIdx.x;
    const float* h = g_H[0] + (size_t)b * R_;
    float acc[O_];
#pragma unroll
    for (int o = 0; o < O_; o++) acc[o] = 0.f;
    for (int r = tid; r < R_; r += 256) {
        float hv = h[r];
#pragma unroll
        for (int o = 0; o < O_; o++) acc[o] += hv * W_out[r * O_ + o];
    }
#pragma unroll
    for (int o = 0; o < O_; o++)
#pragma unroll
        for (int off = 16; off > 0; off >>= 1)
            acc[o] += __shfl_down_sync(0xffffffffu, acc[o], off);
    __shared__ float s[8][O_];
    if ((tid & 31) == 0) {
#pragma unroll
        for (int o = 0; o < O_; o++) s[tid >> 5][o] = acc[o];
    }
    __syncthreads();
    if (tid < O_) {
        float v = b_out[tid];
#pragma unroll
        for (int w = 0; w < 8; w++) v += s[w][tid];
        out[b * O_ + tid] = v;
    }
}

extern "C" void kernel_launch(void* const* d_in, const int* in_sizes, int n_in,
                              void* d_out, int out_size)
{
    const float* x     = (const float*)d_in[0];
    const float* W_in  = (const float*)d_in[1];
    const float* W_res = (const float*)d_in[2];
    const float* W_out = (const float*)d_in[3];
    const float* b_out = (const float*)d_in[4];
    float* out = (float*)d_out;

    esn_zero<<<(B_ * R_ / 4) / 256, 256>>>();

    dim3 grid(R_ / 64, B_ / 64);  // 32 x 4 = 128 CTAs
    for (int t = 0; t < T_; t++)
        esn_step<<<grid, 128>>>(x, W_in, W_res, t);

    esn_readout<<<B_, 256>>>(W_out, b_out, out);
}

// round 3
// speedup vs baseline: 1.2158x; 1.2158x over previous
#include <cuda_runtime.h>
#include <cstdint>

#define B_ 256
#define T_ 512
#define R_ 2048
#define O_ 10

#define CHUNK 4096                 // floats in one 64x64 operand chunk (fragment order)
#define STAGE (2*CHUNK)            // A chunk + B chunk
#define NSTAGE 3
#define SMEM_BYTES (NSTAGE*STAGE*4)

// ---------------- device scratch ----------------
__device__ __align__(128) float g_H[2][B_ * R_];               // fp32 state
__device__ __align__(128) float g_Htf[2][4 * 32 * CHUNK];      // tf32 A operand, fragment order
__device__ __align__(128) float g_Xtf[T_ * 4 * CHUNK];         // tf32 x chunks, fragment order
__device__ __align__(128) float g_Wtf[32 * 33 * CHUNK];        // tf32 B operand, fragment order

__device__ __forceinline__ uint32_t f2tf(float f) {
    uint32_t u; asm("cvt.rna.tf32.f32 %0, %1;" : "=r"(u) : "f"(f)); return u;
}
__device__ __forceinline__ void cp16(void* dst, const void* src) {
    uint32_t d = (uint32_t)__cvta_generic_to_shared(dst);
    asm volatile("cp.async.cg.shared.global [%0], [%1], 16;\n" :: "r"(d), "l"(src));
}

#define MMA(cc, av, bb0, bb1) \
    asm volatile("mma.sync.aligned.m16n8k8.row.col.f32.tf32.tf32.f32 " \
        "{%0,%1,%2,%3},{%4,%5,%6,%7},{%8,%9},{%0,%1,%2,%3};\n" \
        : "+f"((cc)[0]), "+f"((cc)[1]), "+f"((cc)[2]), "+f"((cc)[3]) \
        : "r"((av).x), "r"((av).y), "r"((av).z), "r"((av).w), "r"(bb0), "r"(bb1))

// ---------------- prep: permute + tf32-round operands once ----------------
// Fragment layout per 64x64 chunk: [k8 0..7][half 0..1][lane 0..31][8 floats]
// A lane floats: v = mi*4 + (rhi + 2*khalf); element (m = half*32+mi*16+rhi*8+g, k = k8*8+khalf*4+tg)
// B lane floats: v = ni*2 + r;               element (k = k8*8+r*4+tg,        n = half*32+ni*8+g)
__global__ void prep_W(const float* __restrict__ Wres, const float* __restrict__ Win) {
    uint32_t idx = blockIdx.x * 256u + threadIdx.x;      // 2112*2048
    uint32_t k = idx >> 11, n = idx & 2047u;
    float v = (k < 2048u) ? Wres[(size_t)k * R_ + n] : Win[(size_t)(k - 2048u) * R_ + n];
    uint32_t kc = k >> 6, kl = k & 63u;
    uint32_t k8 = kl >> 3, r = (kl >> 2) & 1u, tg = kl & 3u;
    uint32_t bn = n >> 6, wn = (n >> 5) & 1u, ni = (n >> 3) & 3u, g = n & 7u;
    g_Wtf[(bn * 33u + kc) * CHUNK + k8 * 512u + wn * 256u + (g * 4u + tg) * 8u + ni * 2u + r]
        = __uint_as_float(f2tf(v));
}

__global__ void prep_X(const float* __restrict__ x) {
    uint32_t idx = blockIdx.x * 256u + threadIdx.x;      // 256*512*64
    uint32_t b = idx >> 15, t = (idx >> 6) & 511u, i = idx & 63u;
    float v = x[idx];
    uint32_t bm = b >> 6, wm = (b >> 5) & 1u, mi = (b >> 4) & 1u, rhi = (b >> 3) & 1u, g = b & 7u;
    uint32_t k8 = i >> 3, khalf = (i >> 2) & 1u, tg = i & 3u;
    g_Xtf[(t * 4u + bm) * CHUNK + k8 * 512u + wm * 256u + (g * 4u + tg) * 8u + mi * 4u + rhi + 2u * khalf]
        = __uint_as_float(f2tf(v));
}

__global__ void esn_zero() {
    uint32_t i = blockIdx.x * 256u + threadIdx.x;        // 131072 float4 each
    ((float4*)g_H[0])[i]   = make_float4(0.f, 0.f, 0.f, 0.f);
    ((float4*)g_Htf[0])[i] = make_float4(0.f, 0.f, 0.f, 0.f);
}

// ---------------- step: H_new = 0.5H + 0.5 tanh([H|x_t] @ Wcat) ----------------
__global__ __launch_bounds__(128, 1) void esn_step(int t)
{
    extern __shared__ float sm[];
    const int tid = threadIdx.x, warp = tid >> 5, lane = tid & 31;
    const int wm = warp & 1, wn = warp >> 1;
    const int g = lane >> 2, tg = lane & 3;
    const int bn = blockIdx.x, bm = blockIdx.y;
    const int cur = t & 1, nxt = cur ^ 1;

    const float* __restrict__ aBase = g_Htf[cur] + (size_t)bm * 32 * CHUNK;
    const float* __restrict__ xSrc  = g_Xtf + (size_t)(t * 4 + bm) * CHUNK;
    const float* __restrict__ bBase = g_Wtf + (size_t)bn * 33 * CHUNK;

    float c[2][4][4];
#pragma unroll
    for (int mi = 0; mi < 2; mi++)
#pragma unroll
        for (int ni = 0; ni < 4; ni++)
#pragma unroll
            for (int i = 0; i < 4; i++) c[mi][ni][i] = 0.f;

    auto issue = [&](int kc) {
        float* dst = sm + (kc % 3) * STAGE;
        const float* a = (kc < 32) ? (aBase + (size_t)kc * CHUNK) : xSrc;
        const float* b = bBase + (size_t)kc * CHUNK;
#pragma unroll
        for (int it = 0; it < 8; it++) { int e = (it * 128 + tid) * 4; cp16(dst + e, a + e); }
#pragma unroll
        for (int it = 0; it < 8; it++) { int e = (it * 128 + tid) * 4; cp16(dst + CHUNK + e, b + e); }
        asm volatile("cp.async.commit_group;\n" ::);
    };

    issue(0);
    issue(1);

    for (int kc = 0; kc < 33; kc++) {
        if (kc < 32) asm volatile("cp.async.wait_group 1;\n" ::);
        else         asm volatile("cp.async.wait_group 0;\n" ::);
        __syncthreads();
        if (kc + 2 < 33) issue(kc + 2);

        const uint4* pA = (const uint4*)(sm + (kc % 3) * STAGE + wm * 256) + lane * 2;
        const uint4* pB = (const uint4*)(sm + (kc % 3) * STAGE + CHUNK + wn * 256) + lane * 2;

        uint4 fa[2][2], fb[2][2];
        fa[0][0] = pA[0]; fa[0][1] = pA[1];
        fb[0][0] = pB[0]; fb[0][1] = pB[1];
#pragma unroll
        for (int k8 = 0; k8 < 8; k8++) {
            const int cb = k8 & 1, nb = cb ^ 1;
            if (k8 < 7) {
                fa[nb][0] = pA[(k8 + 1) * 128];     fa[nb][1] = pA[(k8 + 1) * 128 + 1];
                fb[nb][0] = pB[(k8 + 1) * 128];     fb[nb][1] = pB[(k8 + 1) * 128 + 1];
            }
            MMA(c[0][0], fa[cb][0], fb[cb][0].x, fb[cb][0].y);
            MMA(c[0][1], fa[cb][0], fb[cb][0].z, fb[cb][0].w);
            MMA(c[0][2], fa[cb][0], fb[cb][1].x, fb[cb][1].y);
            MMA(c[0][3], fa[cb][0], fb[cb][1].z, fb[cb][1].w);
            MMA(c[1][0], fa[cb][1], fb[cb][0].x, fb[cb][0].y);
            MMA(c[1][1], fa[cb][1], fb[cb][0].z, fb[cb][0].w);
            MMA(c[1][2], fa[cb][1], fb[cb][1].x, fb[cb][1].y);
            MMA(c[1][3], fa[cb][1], fb[cb][1].z, fb[cb][1].w);
        }
    }

    // ---------------- epilogue: leak + tanh, write H fp32 + H tf32(fragment order) ----------------
#pragma unroll
    for (int mi = 0; mi < 2; mi++) {
#pragma unroll
        for (int ni = 0; ni < 4; ni++) {
            const int baserow = bm * 64 + wm * 32 + mi * 16 + g;
            const int c64 = wn * 32 + ni * 8 + tg * 2;
            const int col = bn * 64 + c64;
#pragma unroll
            for (int rhi = 0; rhi < 2; rhi++) {
                const int row = baserow + rhi * 8;
                const float2 ho = *(const float2*)(g_H[cur] + (size_t)row * R_ + col);
                float h0 = 0.5f * ho.x + 0.5f * tanhf(c[mi][ni][2 * rhi]);
                float h1 = 0.5f * ho.y + 0.5f * tanhf(c[mi][ni][2 * rhi + 1]);
                *(float2*)(g_H[nxt] + (size_t)row * R_ + col) = make_float2(h0, h1);
#pragma unroll
                for (int q = 0; q < 2; q++) {
                    const int cc = c64 + q;
                    const int k8p = cc >> 3, tgp = cc & 3, khp = (cc >> 2) & 1;
                    const uint32_t off = (uint32_t)(bm * 32 + bn) * CHUNK + k8p * 512
                        + wm * 256 + (g * 4 + tgp) * 8 + mi * 4 + rhi + 2 * khp;
                    g_Htf[nxt][off] = __uint_as_float(f2tf(q ? h1 : h0));
                }
            }
        }
    }
}

// ---------------- readout ----------------
__global__ void esn_readout(const float* __restrict__ W_out,
                            const float* __restrict__ b_out,
                            float* __restrict__ out)
{
    int b = blockIdx.x, tid = threadIdx.x;
    const float* h = g_H[0] + (size_t)b * R_;
    float acc[O_];
#pragma unroll
    for (int o = 0; o < O_; o++) acc[o] = 0.f;
    for (int r = tid; r < R_; r += 256) {
        float hv = h[r];
#pragma unroll
        for (int o = 0; o < O_; o++) acc[o] += hv * W_out[r * O_ + o];
    }
#pragma unroll
    for (int o = 0; o < O_; o++)
#pragma unroll
        for (int off = 16; off > 0; off >>= 1)
            acc[o] += __shfl_down_sync(0xffffffffu, acc[o], off);
    __shared__ float s[8][O_];
    if ((tid & 31) == 0)
#pragma unroll
        for (int o = 0; o < O_; o++) s[tid >> 5][o] = acc[o];
    __syncthreads();
    if (tid < O_) {
        float v = b_out[tid];
#pragma unroll
        for (int w = 0; w < 8; w++) v += s[w][tid];
        out[b * O_ + tid] = v;
    }
}

extern "C" void kernel_launch(void* const* d_in, const int* in_sizes, int n_in,
                              void* d_out, int out_size)
{
    const float* x     = (const float*)d_in[0];
    const float* W_in  = (const float*)d_in[1];
    const float* W_res = (const float*)d_in[2];
    const float* W_out = (const float*)d_in[3];
    const float* b_out = (const float*)d_in[4];
    float* out = (float*)d_out;

    cudaFuncSetAttribute(esn_step, cudaFuncAttributeMaxDynamicSharedMemorySize, SMEM_BYTES);

    prep_W<<<(2112 * 2048) / 256, 256>>>(W_res, W_in);
    prep_X<<<(B_ * T_ * 64) / 256, 256>>>(x);
    esn_zero<<<512, 256>>>();

    dim3 grid(32, 4);   // bn x bm = 128 CTAs
    for (int t = 0; t < T_; t++)
        esn_step<<<grid, 128, SMEM_BYTES>>>(t);

    esn_readout<<<B_, 256>>>(W_out, b_out, out);
}